// round 3
// baseline (speedup 1.0000x reference)
#include <cuda_runtime.h>
#include <stdint.h>

// PenalizedMSELoss: mean(w * (x - t)^2), w = 3.0 if (4.5 < x < 5.5 && t != 5) else 1.0
// N = 33554432, target stored as int32 (jax x64-disabled; per-warp detect hedges int64).
// Single fused kernel, unroll x4 => 8 independent LDG.128 per iteration.

#define LABEL_V   5
#define PW        3.0f
#define LOWER_V   4.5f
#define UPPER_V   5.5f

#define NBLOCKS   1184          // 148 SMs * 8 CTAs
#define NTHREADS  256

__device__ float         g_partials[NBLOCKS];
__device__ unsigned int  g_counter = 0;

__device__ __forceinline__ float term(float x, int t) {
    float tf  = (float)t;
    float d   = x - tf;
    bool  pen = (x > LOWER_V) & (x < UPPER_V) & (t != LABEL_V);
    float w   = pen ? PW : 1.0f;
    return fmaf(w * d, d, 0.0f);
}

__device__ __forceinline__ float acc4(float a, const float4& xv, const int4& ti) {
    a += term(xv.x, ti.x);
    a += term(xv.y, ti.y);
    a += term(xv.z, ti.z);
    a += term(xv.w, ti.w);
    return a;
}

__device__ __forceinline__ float warp_sum(float v) {
    #pragma unroll
    for (int o = 16; o > 0; o >>= 1)
        v += __shfl_down_sync(0xffffffffu, v, o);
    return v;
}

__device__ __forceinline__ float block_sum(float v, float* ssum) {
    float w = warp_sum(v);
    int lane = threadIdx.x & 31;
    int wid  = threadIdx.x >> 5;
    if (lane == 0) ssum[wid] = w;
    __syncthreads();
    float r = 0.0f;
    if (wid == 0) {
        float t = (lane < NTHREADS / 32) ? ssum[lane] : 0.0f;
        r = warp_sum(t);
    }
    return r;   // valid in warp 0 lane 0
}

__global__ __launch_bounds__(NTHREADS) void mse_fused_kernel(
    const float* __restrict__ x,
    const void*  __restrict__ tv,
    float* __restrict__ out,
    int n, float inv_n)
{
    __shared__ float ssum[NTHREADS / 32];
    __shared__ bool  s_last;

    // ---- per-warp dtype detect (no block barrier, one 128B line) ---------
    // int64 targets (values 0..9) => every odd 32-bit word is zero.
    // int32 targets => 32 uniform samples, P(all zero) ~ 1e-32.
    const int lane = threadIdx.x & 31;
    const int* tw = (const int*)tv;
    unsigned odd_nz = __ballot_sync(0xffffffffu, tw[2 * lane + 1] != 0);
    const bool is64 = (odd_nz == 0u);

    const int tid    = blockIdx.x * blockDim.x + threadIdx.x;
    const int stride = gridDim.x * blockDim.x;
    const int n4     = n >> 2;

    float acc0 = 0.0f, acc1 = 0.0f;
    const float4* __restrict__ x4 = (const float4*)x;

    if (!is64) {
        const int4* __restrict__ t4 = (const int4*)tv;
        int i = tid;
        // main: 8 independent 128-bit streaming loads per iteration
        for (; i + 3 * stride < n4; i += 4 * stride) {
            float4 xa = __ldcs(&x4[i]);
            float4 xb = __ldcs(&x4[i +     stride]);
            float4 xc = __ldcs(&x4[i + 2 * stride]);
            float4 xd = __ldcs(&x4[i + 3 * stride]);
            int4   ta = __ldcs(&t4[i]);
            int4   tb = __ldcs(&t4[i +     stride]);
            int4   tc = __ldcs(&t4[i + 2 * stride]);
            int4   td = __ldcs(&t4[i + 3 * stride]);
            acc0 = acc4(acc0, xa, ta);
            acc1 = acc4(acc1, xb, tb);
            acc0 = acc4(acc0, xc, tc);
            acc1 = acc4(acc1, xd, td);
        }
        // strided remainder (up to 3 iterations)
        for (; i < n4; i += stride) {
            float4 xa = __ldcs(&x4[i]);
            int4   ta = __ldcs(&t4[i]);
            acc0 = acc4(acc0, xa, ta);
        }
        // scalar tail (empty when n % 4 == 0)
        const int* __restrict__ ts = (const int*)tv;
        for (int j = (n4 << 2) + tid; j < n; j += stride)
            acc0 += term(x[j], ts[j]);
    } else {
        const longlong2* __restrict__ t2 = (const longlong2*)tv;
        for (int i = tid; i < n4; i += stride) {
            float4    xv = __ldcs(&x4[i]);
            longlong2 ta = __ldcs(&t2[2 * i]);
            longlong2 tb = __ldcs(&t2[2 * i + 1]);
            acc0 += term(xv.x, (int)ta.x); acc0 += term(xv.y, (int)ta.y);
            acc1 += term(xv.z, (int)tb.x); acc1 += term(xv.w, (int)tb.y);
        }
        const long long* __restrict__ ts = (const long long*)tv;
        for (int j = (n4 << 2) + tid; j < n; j += stride)
            acc0 += term(x[j], (int)ts[j]);
    }

    // ---- block reduce -> partials ---------------------------------------
    float bs = block_sum(acc0 + acc1, ssum);
    if (threadIdx.x == 0) {
        g_partials[blockIdx.x] = bs;
        __threadfence();
        unsigned int done = atomicAdd(&g_counter, 1u);
        s_last = (done == gridDim.x - 1);
    }
    __syncthreads();

    // ---- last arriving block: deterministic final reduce -----------------
    if (s_last) {
        __threadfence();                 // acquire all partials
        float fa = 0.0f;
        for (int i = threadIdx.x; i < NBLOCKS; i += NTHREADS)
            fa += g_partials[i];
        __syncthreads();                 // ssum reuse barrier
        float total = block_sum(fa, ssum);
        if (threadIdx.x == 0) {
            out[0] = total * inv_n;
            g_counter = 0;               // reset for next graph replay
        }
    }
}

extern "C" void kernel_launch(void* const* d_in, const int* in_sizes, int n_in,
                              void* d_out, int out_size)
{
    const float* x  = (const float*)d_in[0];
    const void*  tv = d_in[1];
    float*       out = (float*)d_out;
    int n = in_sizes[0];

    mse_fused_kernel<<<NBLOCKS, NTHREADS>>>(x, tv, out, n, 1.0f / (float)n);
}

// round 5
// speedup vs baseline: 1.0680x; 1.0680x over previous
#include <cuda_runtime.h>
#include <stdint.h>

// PenalizedMSELoss: mean(w * (x - t)^2), w = 3.0 if (4.5 < x < 5.5 && t != 5) else 1.0
// N = 33554432, target stored as int32 in memory (jax x64-disabled).
// Single fused kernel: per-warp dtype detect + grid-stride partials + last-block reduce.
// R5 = R4 resubmit (R4 bench died on container "device busy" before launch).

#define LABEL_V   5
#define PW        3.0f
#define LOWER_V   4.5f
#define UPPER_V   5.5f

#define NBLOCKS   1184          // 148 SMs * 8 CTAs resident
#define NTHREADS  256

__device__ float         g_partials[NBLOCKS];
__device__ unsigned int  g_counter = 0;

__device__ __forceinline__ float term(float x, int t) {
    float tf  = (float)t;
    float d   = x - tf;
    bool  pen = (x > LOWER_V) & (x < UPPER_V) & (t != LABEL_V);
    float w   = pen ? PW : 1.0f;
    return w * d * d;
}

__device__ __forceinline__ float acc4(float a, const float4& xv, const int4& ti) {
    a += term(xv.x, ti.x);
    a += term(xv.y, ti.y);
    a += term(xv.z, ti.z);
    a += term(xv.w, ti.w);
    return a;
}

__device__ __forceinline__ float warp_sum(float v) {
    #pragma unroll
    for (int o = 16; o > 0; o >>= 1)
        v += __shfl_down_sync(0xffffffffu, v, o);
    return v;
}

__device__ __forceinline__ float block_sum(float v, float* ssum) {
    float w = warp_sum(v);
    int lane = threadIdx.x & 31;
    int wid  = threadIdx.x >> 5;
    if (lane == 0) ssum[wid] = w;
    __syncthreads();
    float r = 0.0f;
    if (wid == 0) {
        float t = (lane < NTHREADS / 32) ? ssum[lane] : 0.0f;
        r = warp_sum(t);
    }
    return r;   // valid in warp 0 lane 0
}

__global__ __launch_bounds__(NTHREADS, 8) void mse_fused_kernel(
    const float* __restrict__ x,
    const void*  __restrict__ tv,
    float* __restrict__ out,
    int n, float inv_n)
{
    __shared__ float ssum[NTHREADS / 32];
    __shared__ bool  s_last;

    // ---- per-warp dtype detect (one 128B line, no block barrier) ---------
    // int64 targets (values 0..9) => every odd 32-bit word is zero.
    const int lane = threadIdx.x & 31;
    const int* tw = (const int*)tv;
    unsigned odd_nz = __ballot_sync(0xffffffffu, tw[2 * lane + 1] != 0);
    const bool is64 = (odd_nz == 0u);

    const int tid    = blockIdx.x * blockDim.x + threadIdx.x;
    const int stride = gridDim.x * blockDim.x;
    const int n4     = n >> 2;   // # of float4 elements
    const int n8     = n >> 3;   // # of float4 PAIRS

    float acc0 = 0.0f, acc1 = 0.0f;
    const float4* __restrict__ x4 = (const float4*)x;

    if (!is64) {
        const int4* __restrict__ t4 = (const int4*)tv;
        // main: each thread owns pair p -> 4 independent LDG.128,
        // 2 base addresses with +16B immediate offsets.
        for (int p = tid; p < n8; p += stride) {
            const float4* __restrict__ xb = &x4[2 * p];
            const int4*   __restrict__ tb = &t4[2 * p];
            float4 xa = __ldcs(xb);
            float4 xc = __ldcs(xb + 1);
            int4   ta = __ldcs(tb);
            int4   tc = __ldcs(tb + 1);
            acc0 = acc4(acc0, xa, ta);
            acc1 = acc4(acc1, xc, tc);
        }
        // leftover float4 (when n4 odd)
        const int4* __restrict__ t4s = (const int4*)tv;
        for (int i = (n8 << 1) + tid; i < n4; i += stride) {
            float4 xa = __ldcs(&x4[i]);
            int4   ta = __ldcs(&t4s[i]);
            acc0 = acc4(acc0, xa, ta);
        }
        // scalar tail (when n % 4 != 0)
        const int* __restrict__ ts = (const int*)tv;
        for (int j = (n4 << 2) + tid; j < n; j += stride)
            acc0 += term(x[j], ts[j]);
    } else {
        const longlong2* __restrict__ t2 = (const longlong2*)tv;
        for (int i = tid; i < n4; i += stride) {
            float4    xv = __ldcs(&x4[i]);
            longlong2 ta = __ldcs(&t2[2 * i]);
            longlong2 tb = __ldcs(&t2[2 * i + 1]);
            acc0 += term(xv.x, (int)ta.x); acc0 += term(xv.y, (int)ta.y);
            acc1 += term(xv.z, (int)tb.x); acc1 += term(xv.w, (int)tb.y);
        }
        const long long* __restrict__ ts = (const long long*)tv;
        for (int j = (n4 << 2) + tid; j < n; j += stride)
            acc0 += term(x[j], (int)ts[j]);
    }

    // ---- block reduce -> partials ---------------------------------------
    float bs = block_sum(acc0 + acc1, ssum);
    if (threadIdx.x == 0) {
        g_partials[blockIdx.x] = bs;
        __threadfence();
        unsigned int done = atomicAdd(&g_counter, 1u);
        s_last = (done == gridDim.x - 1);
    }
    __syncthreads();

    // ---- last arriving block: deterministic final reduce -----------------
    if (s_last) {
        __threadfence();                 // acquire all partials
        float fa = 0.0f;
        for (int i = threadIdx.x; i < NBLOCKS; i += NTHREADS)
            fa += g_partials[i];
        __syncthreads();                 // ssum reuse barrier
        float total = block_sum(fa, ssum);
        if (threadIdx.x == 0) {
            out[0] = total * inv_n;
            __threadfence();
            g_counter = 0;               // reset for next graph replay
        }
    }
}

extern "C" void kernel_launch(void* const* d_in, const int* in_sizes, int n_in,
                              void* d_out, int out_size)
{
    const float* x  = (const float*)d_in[0];
    const void*  tv = d_in[1];
    float*       out = (float*)d_out;
    int n = in_sizes[0];

    mse_fused_kernel<<<NBLOCKS, NTHREADS>>>(x, tv, out, n, 1.0f / (float)n);
}

// round 6
// speedup vs baseline: 1.1250x; 1.0534x over previous
#include <cuda_runtime.h>
#include <stdint.h>

// PenalizedMSELoss: mean(w * (x - t)^2), w = 3.0 if (4.5 < x < 5.5 && t != 5) else 1.0
// N = 33554432, target stored as int32 in memory (jax x64-disabled; detect hedges int64).
// R6: R2 loop (lane-contiguous LDG.128, strided unroll x2) + occupancy pin +
//     distributed per-warp dtype detect (no L2 hotspot).

#define LABEL_V   5
#define PW        3.0f
#define LOWER_V   4.5f
#define UPPER_V   5.5f

#define NBLOCKS   1184          // 148 SMs * 8 CTAs resident
#define NTHREADS  256

__device__ float         g_partials[NBLOCKS];
__device__ unsigned int  g_counter = 0;

__device__ __forceinline__ float term(float x, int t) {
    float tf  = (float)t;
    float d   = x - tf;
    bool  pen = (x > LOWER_V) & (x < UPPER_V) & (t != LABEL_V);
    float w   = pen ? PW : 1.0f;
    return w * d * d;
}

__device__ __forceinline__ float acc4(float a, const float4& xv, const int4& ti) {
    a += term(xv.x, ti.x);
    a += term(xv.y, ti.y);
    a += term(xv.z, ti.z);
    a += term(xv.w, ti.w);
    return a;
}

__device__ __forceinline__ float warp_sum(float v) {
    #pragma unroll
    for (int o = 16; o > 0; o >>= 1)
        v += __shfl_down_sync(0xffffffffu, v, o);
    return v;
}

__device__ __forceinline__ float block_sum(float v, float* ssum) {
    float w = warp_sum(v);
    int lane = threadIdx.x & 31;
    int wid  = threadIdx.x >> 5;
    if (lane == 0) ssum[wid] = w;
    __syncthreads();
    float r = 0.0f;
    if (wid == 0) {
        float t = (lane < NTHREADS / 32) ? ssum[lane] : 0.0f;
        r = warp_sum(t);
    }
    return r;   // valid in warp 0 lane 0
}

__global__ __launch_bounds__(NTHREADS, 8) void mse_fused_kernel(
    const float* __restrict__ x,
    const void*  __restrict__ tv,
    float* __restrict__ out,
    int n, float inv_n)
{
    __shared__ float ssum[NTHREADS / 32];
    __shared__ bool  s_last;

    const int lane = threadIdx.x & 31;
    const int tid    = blockIdx.x * blockDim.x + threadIdx.x;
    const int stride = gridDim.x * blockDim.x;

    // ---- distributed per-warp dtype detect -------------------------------
    // int64 targets (values 0..9) => every odd 32-bit word is zero.
    // Each warp samples odd words in its OWN slice -> requests spread across
    // all LTS slices (no single-line hotspot), P(int32 all-zero) ~ 1e-32.
    // Max word index: 2*(9472*32 - 1) + 1 < 606208 << N, valid either layout.
    const int gwarp = tid >> 5;
    const int* tw = (const int*)tv;
    unsigned odd_nz = __ballot_sync(0xffffffffu, tw[2 * (gwarp * 32 + lane) + 1] != 0);
    const bool is64 = (odd_nz == 0u);

    const int n4 = n >> 2;   // # of float4 elements

    float acc0 = 0.0f, acc1 = 0.0f;
    const float4* __restrict__ x4 = (const float4*)x;

    if (!is64) {
        const int4* __restrict__ t4 = (const int4*)tv;
        int i = tid;
        // 4 independent lane-contiguous LDG.128 per iteration (each
        // instruction: 32 lanes x 16B contiguous = 512B wavefront).
        for (; i + stride < n4; i += 2 * stride) {
            float4 xa = __ldcs(&x4[i]);
            float4 xb = __ldcs(&x4[i + stride]);
            int4   ta = __ldcs(&t4[i]);
            int4   tb = __ldcs(&t4[i + stride]);
            acc0 = acc4(acc0, xa, ta);
            acc1 = acc4(acc1, xb, tb);
        }
        if (i < n4) {
            float4 xa = __ldcs(&x4[i]);
            int4   ta = __ldcs(&t4[i]);
            acc0 = acc4(acc0, xa, ta);
        }
        // scalar tail (empty when n % 4 == 0)
        const int* __restrict__ ts = (const int*)tv;
        for (int j = (n4 << 2) + tid; j < n; j += stride)
            acc0 += term(x[j], ts[j]);
    } else {
        const longlong2* __restrict__ t2 = (const longlong2*)tv;
        for (int i = tid; i < n4; i += stride) {
            float4    xv = __ldcs(&x4[i]);
            longlong2 ta = __ldcs(&t2[2 * i]);
            longlong2 tb = __ldcs(&t2[2 * i + 1]);
            acc0 += term(xv.x, (int)ta.x); acc0 += term(xv.y, (int)ta.y);
            acc1 += term(xv.z, (int)tb.x); acc1 += term(xv.w, (int)tb.y);
        }
        const long long* __restrict__ ts = (const long long*)tv;
        for (int j = (n4 << 2) + tid; j < n; j += stride)
            acc0 += term(x[j], (int)ts[j]);
    }

    // ---- block reduce -> partials ---------------------------------------
    float bs = block_sum(acc0 + acc1, ssum);
    if (threadIdx.x == 0) {
        g_partials[blockIdx.x] = bs;
        __threadfence();
        unsigned int done = atomicAdd(&g_counter, 1u);
        s_last = (done == gridDim.x - 1);
    }
    __syncthreads();

    // ---- last arriving block: deterministic final reduce -----------------
    if (s_last) {
        __threadfence();                 // acquire all partials
        float fa = 0.0f;
        for (int i = threadIdx.x; i < NBLOCKS; i += NTHREADS)
            fa += g_partials[i];
        __syncthreads();                 // ssum reuse barrier
        float total = block_sum(fa, ssum);
        if (threadIdx.x == 0) {
            out[0] = total * inv_n;
            __threadfence();
            g_counter = 0;               // reset for next graph replay
        }
    }
}

extern "C" void kernel_launch(void* const* d_in, const int* in_sizes, int n_in,
                              void* d_out, int out_size)
{
    const float* x  = (const float*)d_in[0];
    const void*  tv = d_in[1];
    float*       out = (float*)d_out;
    int n = in_sizes[0];

    mse_fused_kernel<<<NBLOCKS, NTHREADS>>>(x, tv, out, n, 1.0f / (float)n);
}